// round 11
// baseline (speedup 1.0000x reference)
#include <cuda_runtime.h>
typedef unsigned long long u64;
typedef unsigned int u32;

__device__ __forceinline__ u64 pk2(float a,float b){u64 r;asm("mov.b64 %0,{%1,%2};":"=l"(r):"f"(a),"f"(b));return r;}
__device__ __forceinline__ void unpk(u64 v,float&a,float&b){asm("mov.b64 {%0,%1},%2;":"=f"(a),"=f"(b):"l"(v));}
__device__ __forceinline__ u64 dup2(float a){u64 r;asm("mov.b64 %0,{%1,%1};":"=l"(r):"f"(a));return r;}
__device__ __forceinline__ u64 ffma2(u64 a,u64 b,u64 c){u64 d;asm("fma.rn.f32x2 %0,%1,%2,%3;":"=l"(d):"l"(a),"l"(b),"l"(c));return d;}
__device__ __forceinline__ u64 fadd2(u64 a,u64 b){u64 d;asm("add.rn.f32x2 %0,%1,%2;":"=l"(d):"l"(a),"l"(b));return d;}
__device__ __forceinline__ u64 frelu2(u64 x){float a,b;unpk(x,a,b);return pk2(fmaxf(a,0.f),fmaxf(b,0.f));}
__device__ __forceinline__ u32 f2t(float x){u32 r;asm("cvt.rna.tf32.f32 %0,%1;":"=r"(r):"f"(x));return r;}
__device__ __forceinline__ void mma_k4(float&d0,float&d1,float&d2,float&d3,u32 a0,u32 a1,u32 b0){
    asm("mma.sync.aligned.m16n8k4.row.col.f32.tf32.tf32.f32 {%0,%1,%2,%3},{%4,%5},{%6},{%0,%1,%2,%3};"
        :"+f"(d0),"+f"(d1),"+f"(d2),"+f"(d3):"r"(a0),"r"(a1),"r"(b0));}
__device__ __forceinline__ void mma_k8(float&d0,float&d1,float&d2,float&d3,u32 a0,u32 a1,u32 a2,u32 a3,u32 b0,u32 b1){
    asm("mma.sync.aligned.m16n8k8.row.col.f32.tf32.tf32.f32 {%0,%1,%2,%3},{%4,%5,%6,%7},{%8,%9},{%0,%1,%2,%3};"
        :"+f"(d0),"+f"(d1),"+f"(d2),"+f"(d3):"r"(a0),"r"(a1),"r"(a2),"r"(a3),"r"(b0),"r"(b1));}

// byte offsets in dynamic smem
#define B_SSUM 0          // float [1024][40]
#define B_BP2  163840     // uint2 [16kc][5nt][32]  W2 frag pack (k-permuted)
#define B_BP1  184320     // u32   [16nt][32]       W1 frag pack
#define B_CE2  186368     // float2[4][64]          folded L1 bias pairs
#define B_B2P  188416     // float2[20]             b2 pairs (pad 0)
#define B_PB   188576     // u64 phase-B tables (4788)
#define SMEM_TOTAL 226880
// pb u64-offsets
#define PB_W3P 0
#define PB_B3 2560
#define PB_WMVP 2688
#define PB_BMP 3712
#define PB_BVP 3716
#define PB_WD1 3720
#define PB_WD2T 4360
#define PB_BD1 4744
#define PB_BD2 4776

__global__ void __launch_bounds__(512)
vae_kernel(const float* __restrict__ initial_c, const float* __restrict__ current_c,
           const float* __restrict__ eps,
           const float* __restrict__ W1, const float* __restrict__ b1,
           const float* __restrict__ W2, const float* __restrict__ b2,
           const float* __restrict__ W3, const float* __restrict__ b3,
           const float* __restrict__ Wm, const float* __restrict__ bm,
           const float* __restrict__ Wv, const float* __restrict__ bv,
           const float* __restrict__ Wd1, const float* __restrict__ bd1,
           const float* __restrict__ Wd2, const float* __restrict__ bd2,
           float* __restrict__ out, int bsz)
{
    extern __shared__ __align__(16) char smem[];
    float*  ssum = (float*)(smem + B_SSUM);
    uint2*  bp2  = (uint2*)(smem + B_BP2);
    u32*    bp1  = (u32*)(smem + B_BP1);
    float2* ce2  = (float2*)(smem + B_CE2);
    float2* b2p  = (float2*)(smem + B_B2P);
    u64*    pb   = (u64*)(smem + B_PB);
    const int tid = threadIdx.x;

    // ---------------- table fills ----------------
    for (int i = tid; i < 256; i += 512) {        // ce2: folded L1 bias
        int e = i >> 6, c = i & 63; int k0 = 2*c, k1 = 2*c+1;
        ce2[i] = make_float2(b1[k0]+W1[k0*13]+W1[k0*13+6+e],
                             b1[k1]+W1[k1*13]+W1[k1*13+6+e]);
    }
    {   int i = tid;                               // bp1 (512 entries)
        if (i < 512) { int lane=i&31, n=8*(i>>5)+(lane>>2), k=lane&3;
            bp1[i] = (k<3) ? f2t(W1[n*13+10+k]) : 0u; }
    }
    for (int i = tid; i < 2560; i += 512) {       // bp2, k-permuted W2 frags
        int lane = i & 31, kcnt = i >> 5;
        int kc = kcnt/5, nt = kcnt - 5*kc;
        int j = 8*nt + (lane>>2), h0 = 8*kc + 2*(lane&3);
        uint2 v;
        v.x = (j<39) ? f2t(W2[j*128+h0])   : 0u;
        v.y = (j<39) ? f2t(W2[j*128+h0+1]) : 0u;
        bp2[i] = v;
    }
    if (tid < 20) b2p[tid] = make_float2(b2[2*tid], (2*tid+1<39)? b2[2*tid+1] : 0.f);
    for (int i = tid; i < 2560; i += 512) { int k=i/20, jp=i-k*20; int j0=2*jp, j1=j0+1;
        ((float2*)(pb+PB_W3P))[i] = make_float2(j0<39?W3[k*39+j0]:0.f, j1<39?W3[k*39+j1]:0.f); }
    if (tid < 128) { float v=b3[tid]; ((float2*)(pb+PB_B3))[tid]=make_float2(v,v); }
    for (int i = tid; i < 1024; i += 512) { int k=i>>3, o=i&7; float a,b;
        if (o<4){a=Wm[(2*o)*128+k]; b=Wm[(2*o+1)*128+k];}
        else {int oo=o-4; a=Wv[(2*oo)*128+k]; b=Wv[(2*oo+1)*128+k];}
        ((float2*)(pb+PB_WMVP))[i]=make_float2(a,b); }
    if (tid < 4) { ((float2*)(pb+PB_BMP))[tid]=make_float2(bm[2*tid],bm[2*tid+1]);
                   ((float2*)(pb+PB_BVP))[tid]=make_float2(bv[2*tid],bv[2*tid+1]); }
    for (int i = tid; i < 640; i += 512) { int u=i/20, t=i-u*20; float v=Wd1[u*25+5+t];
        ((float2*)(pb+PB_WD1))[i]=make_float2(v,v); }
    if (tid < 384) { int u=tid/12, r=tid-u*12; float v=Wd2[r*32+u];
        ((float2*)(pb+PB_WD2T))[tid]=make_float2(v,v); }
    if (tid < 32) { float v=bd1[tid]+Wd1[tid*25]; ((float2*)(pb+PB_BD1))[tid]=make_float2(v,v); }
    if (tid < 12) { float v=bd2[tid]; ((float2*)(pb+PB_BD2))[tid]=make_float2(v,v); }
    __syncthreads();

    const int S0 = blockIdx.x * 1024;

    // ---------------- phase A: edge MLP via tf32 mma ----------------
    {
        const int w = tid >> 5, lane = tid & 31;
        const int q = lane & 3, r = lane >> 2;
#pragma unroll 1
        for (int i = 0; i < 4; i++) {
            const int lm = (w*4+i)*16;
            const int slo = S0 + lm + r, shi = slo + 8;
            float xl[4], xh[4];
#pragma unroll
            for (int e = 0; e < 4; e++) {
                int pidx = (q==0)? e : (q==1)? 10+e : 14+4*e;
                xl[e] = (q<3)? current_c[(size_t)slo*30+pidx] : 0.f;
                xh[e] = (q<3)? current_c[(size_t)shi*30+pidx] : 0.f;
            }
            float2 b2f[5];
#pragma unroll
            for (int n = 0; n < 5; n++) b2f[n] = b2p[4*n+q];
            float ss[5][4];
#pragma unroll
            for (int n=0;n<5;n++){ss[n][0]=0.f;ss[n][1]=0.f;ss[n][2]=0.f;ss[n][3]=0.f;}
#pragma unroll 1
            for (int e = 0; e < 4; e++) {
                u32 xa0 = f2t(xl[e]), xa1 = f2t(xh[e]);
                float D[5][4];
#pragma unroll
                for (int n=0;n<5;n++){D[n][0]=0.f;D[n][1]=0.f;D[n][2]=0.f;D[n][3]=0.f;}
#pragma unroll
                for (int kc = 0; kc < 16; kc++) {
                    float2 cef = ce2[e*64 + kc*4 + q];
                    float d0=cef.x, d1=cef.y, d2=cef.x, d3=cef.y;
                    mma_k4(d0,d1,d2,d3, xa0, xa1, bp1[kc*32+lane]);
                    // relu + cvt; D->A slot permutation absorbed in bp2
                    u32 f0=f2t(fmaxf(d0,0.f)), f1=f2t(fmaxf(d2,0.f));
                    u32 g0=f2t(fmaxf(d1,0.f)), g1=f2t(fmaxf(d3,0.f));
                    const uint2* bb = bp2 + (kc*5)*32 + lane;
#pragma unroll
                    for (int n=0;n<5;n++) {
                        uint2 b = bb[n*32];
                        mma_k8(D[n][0],D[n][1],D[n][2],D[n][3], f0,f1,g0,g1, b.x,b.y);
                    }
                }
#pragma unroll
                for (int n=0;n<5;n++) {
                    ss[n][0] += fmaxf(D[n][0]+b2f[n].x, 0.f);
                    ss[n][1] += fmaxf(D[n][1]+b2f[n].y, 0.f);
                    ss[n][2] += fmaxf(D[n][2]+b2f[n].x, 0.f);
                    ss[n][3] += fmaxf(D[n][3]+b2f[n].y, 0.f);
                }
            }
#pragma unroll
            for (int n=0;n<5;n++) {
                int c = 8*n + 2*q;
                *(float2*)(ssum + (lm+r)*40 + c)   = make_float2(ss[n][0], ss[n][1]);
                *(float2*)(ssum + (lm+r+8)*40 + c) = make_float2(ss[n][2], ss[n][3]);
            }
        }
    }
    __syncthreads();

    // ---------------- phase B: trunk + heads + decoder (f32x2 scalar) ----------------
    const int r0 = S0 + tid, r1 = r0 + 512;
    u64 s400[20], s401[20];
    {
        const u64* a = (const u64*)(ssum + tid*40);
        const u64* b = (const u64*)(ssum + (tid+512)*40);
#pragma unroll
        for (int jp = 0; jp < 20; jp++) { s400[jp]=a[jp]; s401[jp]=b[jp]; }
    }
    u64 mc0[4], mc1[4], vc0[4], vc1[4];
#pragma unroll
    for (int q = 0; q < 4; q++) {
        mc0[q] = pb[PB_BMP + q]; mc1[q] = mc0[q];
        vc0[q] = pb[PB_BVP + q]; vc1[q] = vc0[q];
    }
#pragma unroll 2
    for (int k = 0; k < 128; k++) {
        const ulonglong2* w3 = (const ulonglong2*)(pb + PB_W3P + k*20);
        u64 c0a=0ull, c0b=0ull, c1a=0ull, c1b=0ull;
#pragma unroll
        for (int q = 0; q < 10; q++) {
            ulonglong2 ww = w3[q];
            c0a = ffma2(s400[2*q],   ww.x, c0a);
            c0b = ffma2(s400[2*q+1], ww.y, c0b);
            c1a = ffma2(s401[2*q],   ww.x, c1a);
            c1b = ffma2(s401[2*q+1], ww.y, c1b);
        }
        u64 t0 = fadd2(c0a,c0b), t1 = fadd2(c1a,c1b);
        float x0,y0,x1,y1; unpk(t0,x0,y0); unpk(t1,x1,y1);
        u64 h = pk2(x0+y0, x1+y1);
        h = fadd2(h, pb[PB_B3 + k]);
        h = frelu2(h);
        float h0,h1; unpk(h,h0,h1);
        u64 H0 = dup2(h0), H1 = dup2(h1);
        const ulonglong2* wmv = (const ulonglong2*)(pb + PB_WMVP + k*8);
        ulonglong2 wa=wmv[0], wb=wmv[1], wc=wmv[2], wd=wmv[3];
        mc0[0]=ffma2(H0,wa.x,mc0[0]); mc0[1]=ffma2(H0,wa.y,mc0[1]);
        mc0[2]=ffma2(H0,wb.x,mc0[2]); mc0[3]=ffma2(H0,wb.y,mc0[3]);
        mc1[0]=ffma2(H1,wa.x,mc1[0]); mc1[1]=ffma2(H1,wa.y,mc1[1]);
        mc1[2]=ffma2(H1,wb.x,mc1[2]); mc1[3]=ffma2(H1,wb.y,mc1[3]);
        vc0[0]=ffma2(H0,wc.x,vc0[0]); vc0[1]=ffma2(H0,wc.y,vc0[1]);
        vc0[2]=ffma2(H0,wd.x,vc0[2]); vc0[3]=ffma2(H0,wd.y,vc0[3]);
        vc1[0]=ffma2(H1,wc.x,vc1[0]); vc1[1]=ffma2(H1,wc.y,vc1[1]);
        vc1[2]=ffma2(H1,wd.x,vc1[2]); vc1[3]=ffma2(H1,wd.y,vc1[3]);
    }
    float me0[8], me1[8], lv0[8], lv1[8];
#pragma unroll
    for (int q = 0; q < 4; q++) {
        unpk(mc0[q], me0[2*q], me0[2*q+1]);
        unpk(mc1[q], me1[2*q], me1[2*q+1]);
        unpk(vc0[q], lv0[2*q], lv0[2*q+1]);
        unpk(vc1[q], lv1[2*q], lv1[2*q+1]);
    }
    const float4* e40 = (const float4*)(eps + (size_t)r0*8);
    const float4* e41 = (const float4*)(eps + (size_t)r1*8);
    float4 ea0=e40[0], eb0=e40[1], ea1=e41[0], eb1=e41[1];
    float ep0[8] = {ea0.x,ea0.y,ea0.z,ea0.w, eb0.x,eb0.y,eb0.z,eb0.w};
    float ep1[8] = {ea1.x,ea1.y,ea1.z,ea1.w, eb1.x,eb1.y,eb1.z,eb1.w};
    float z0[8], z1[8]; u64 zq[8];
#pragma unroll
    for (int o = 0; o < 8; o++) {
        z0[o] = ep0[o]*__expf(0.5f*lv0[o]) + me0[o];
        z1[o] = ep1[o]*__expf(0.5f*lv1[o]) + me1[o];
        zq[o] = pk2(z0[o], z1[o]);
    }
    {
        float4* om0=(float4*)(out+(size_t)bsz*12+(size_t)r0*8);
        float4* om1=(float4*)(out+(size_t)bsz*12+(size_t)r1*8);
        float4* ov0=(float4*)(out+(size_t)bsz*20+(size_t)r0*8);
        float4* ov1=(float4*)(out+(size_t)bsz*20+(size_t)r1*8);
        float4* oz0=(float4*)(out+(size_t)bsz*28+(size_t)r0*8);
        float4* oz1=(float4*)(out+(size_t)bsz*28+(size_t)r1*8);
        om0[0]=make_float4(me0[0],me0[1],me0[2],me0[3]); om0[1]=make_float4(me0[4],me0[5],me0[6],me0[7]);
        om1[0]=make_float4(me1[0],me1[1],me1[2],me1[3]); om1[1]=make_float4(me1[4],me1[5],me1[6],me1[7]);
        ov0[0]=make_float4(lv0[0],lv0[1],lv0[2],lv0[3]); ov0[1]=make_float4(lv0[4],lv0[5],lv0[6],lv0[7]);
        ov1[0]=make_float4(lv1[0],lv1[1],lv1[2],lv1[3]); ov1[1]=make_float4(lv1[4],lv1[5],lv1[6],lv1[7]);
        oz0[0]=make_float4(z0[0],z0[1],z0[2],z0[3]);     oz0[1]=make_float4(z0[4],z0[5],z0[6],z0[7]);
        oz1[0]=make_float4(z1[0],z1[1],z1[2],z1[3]);     oz1[1]=make_float4(z1[4],z1[5],z1[6],z1[7]);
    }
    const float* i0 = initial_c + (size_t)r0*30;
    const float* i1 = initial_c + (size_t)r1*30;
    u64 ic[12];
    {
        const int OID[12] = {0,1,2,3,10,11,12,13,14,18,22,26};
#pragma unroll
        for (int t = 0; t < 12; t++) ic[t] = pk2(i0[OID[t]], i1[OID[t]]);
    }
    u64 d12[12];
#pragma unroll
    for (int r = 0; r < 12; r++) d12[r] = pb[PB_BD2 + r];
#pragma unroll 4
    for (int u = 0; u < 32; u++) {
        u64 t = pb[PB_BD1 + u];
        const ulonglong2* w = (const ulonglong2*)(pb + PB_WD1 + u*20);
#pragma unroll
        for (int q = 0; q < 6; q++) {
            ulonglong2 ww = w[q];
            t = ffma2(ic[2*q],   ww.x, t);
            t = ffma2(ic[2*q+1], ww.y, t);
        }
#pragma unroll
        for (int q = 6; q < 10; q++) {
            ulonglong2 ww = w[q];
            t = ffma2(zq[2*(q-6)],   ww.x, t);
            t = ffma2(zq[2*(q-6)+1], ww.y, t);
        }
        t = frelu2(t);
        const ulonglong2* w2 = (const ulonglong2*)(pb + PB_WD2T + u*12);
#pragma unroll
        for (int q = 0; q < 6; q++) {
            ulonglong2 ww = w2[q];
            d12[2*q]   = ffma2(t, ww.x, d12[2*q]);
            d12[2*q+1] = ffma2(t, ww.y, d12[2*q+1]);
        }
    }
    {
        float o0[12], o1[12];
#pragma unroll
        for (int r = 0; r < 12; r++) {
            float x0,x1; unpk(d12[r],x0,x1);
            o0[r] = 1.f/(1.f+__expf(-x0));
            o1[r] = 1.f/(1.f+__expf(-x1));
        }
        float4* p0 = (float4*)(out + (size_t)r0*12);
        float4* p1 = (float4*)(out + (size_t)r1*12);
        p0[0]=make_float4(o0[0],o0[1],o0[2],o0[3]);
        p0[1]=make_float4(o0[4],o0[5],o0[6],o0[7]);
        p0[2]=make_float4(o0[8],o0[9],o0[10],o0[11]);
        p1[0]=make_float4(o1[0],o1[1],o1[2],o1[3]);
        p1[1]=make_float4(o1[4],o1[5],o1[6],o1[7]);
        p1[2]=make_float4(o1[8],o1[9],o1[10],o1[11]);
    }
}

extern "C" void kernel_launch(void* const* d_in, const int* in_sizes, int n_in,
                              void* d_out, int out_size) {
    const float* initial_c = (const float*)d_in[0];
    const float* current_c = (const float*)d_in[2];
    const float* eps       = (const float*)d_in[3];
    const float* W1  = (const float*)d_in[4];
    const float* b1  = (const float*)d_in[5];
    const float* W2  = (const float*)d_in[6];
    const float* b2  = (const float*)d_in[7];
    const float* W3  = (const float*)d_in[8];
    const float* b3  = (const float*)d_in[9];
    const float* Wm  = (const float*)d_in[10];
    const float* bm  = (const float*)d_in[11];
    const float* Wv  = (const float*)d_in[12];
    const float* bv  = (const float*)d_in[13];
    const float* Wd1 = (const float*)d_in[14];
    const float* bd1 = (const float*)d_in[15];
    const float* Wd2 = (const float*)d_in[16];
    const float* bd2 = (const float*)d_in[17];
    float* out = (float*)d_out;

    int bsz = in_sizes[3] / 8;
    cudaFuncSetAttribute(vae_kernel, cudaFuncAttributeMaxDynamicSharedMemorySize, SMEM_TOTAL);
    int blocks = bsz / 1024;
    vae_kernel<<<blocks, 512, SMEM_TOTAL>>>(
        initial_c, current_c, eps,
        W1, b1, W2, b2, W3, b3, Wm, bm, Wv, bv, Wd1, bd1, Wd2, bd2,
        out, bsz);
}

// round 13
// speedup vs baseline: 1.3761x; 1.3761x over previous
#include <cuda_runtime.h>
typedef unsigned long long u64;
typedef unsigned int u32;

#define NB 262144
__device__ u64 g_scr[20 * NB];   // [jp][B] edge-MLP outputs as f32x2 j-pairs

__device__ __forceinline__ u64 pk2(float a,float b){u64 r;asm("mov.b64 %0,{%1,%2};":"=l"(r):"f"(a),"f"(b));return r;}
__device__ __forceinline__ void unpk(u64 v,float&a,float&b){asm("mov.b64 {%0,%1},%2;":"=f"(a),"=f"(b):"l"(v));}
__device__ __forceinline__ u64 dup2(float a){u64 r;asm("mov.b64 %0,{%1,%1};":"=l"(r):"f"(a));return r;}
__device__ __forceinline__ u64 ffma2(u64 a,u64 b,u64 c){u64 d;asm("fma.rn.f32x2 %0,%1,%2,%3;":"=l"(d):"l"(a),"l"(b),"l"(c));return d;}
__device__ __forceinline__ u64 fadd2(u64 a,u64 b){u64 d;asm("add.rn.f32x2 %0,%1,%2;":"=l"(d):"l"(a),"l"(b));return d;}
__device__ __forceinline__ u32 f2t(float x){u32 r;asm("cvt.rna.tf32.f32 %0,%1;":"=r"(r):"f"(x));return r;}
__device__ __forceinline__ void mma_k4(float&d0,float&d1,float&d2,float&d3,u32 a0,u32 a1,u32 b0){
    asm("mma.sync.aligned.m16n8k4.row.col.f32.tf32.tf32.f32 {%0,%1,%2,%3},{%4,%5},{%6},{%0,%1,%2,%3};"
        :"+f"(d0),"+f"(d1),"+f"(d2),"+f"(d3):"r"(a0),"r"(a1),"r"(b0));}
__device__ __forceinline__ void mma_k8(float&d0,float&d1,float&d2,float&d3,u32 a0,u32 a1,u32 a2,u32 a3,u32 b0,u32 b1){
    asm("mma.sync.aligned.m16n8k8.row.col.f32.tf32.tf32.f32 {%0,%1,%2,%3},{%4,%5,%6,%7},{%8,%9},{%0,%1,%2,%3};"
        :"+f"(d0),"+f"(d1),"+f"(d2),"+f"(d3):"r"(a0),"r"(a1),"r"(a2),"r"(a3),"r"(b0),"r"(b1));}

// ================= Kernel A: edge MLP via tf32 mma =================
__global__ void __launch_bounds__(256, 3)
edge_kernel(const float* __restrict__ current_c,
            const float* __restrict__ W1, const float* __restrict__ b1,
            const float* __restrict__ W2, const float* __restrict__ b2, int bsz)
{
    __shared__ uint2  bp2[2560];   // [16kc][5nt][32] W2 frag pack (k-permuted)
    __shared__ u32    bp1[512];    // [16kc][32]      W1 frag pack
    __shared__ float2 ce2[256];    // [4e][64]        folded L1 bias pairs
    __shared__ float2 b2p[20];
    const int tid = threadIdx.x;

    for (int i = tid; i < 256; i += 256) { int e=i>>6, c=i&63; int k0=2*c, k1=k0+1;
        ce2[i] = make_float2(b1[k0]+W1[k0*13]+W1[k0*13+6+e],
                             b1[k1]+W1[k1*13]+W1[k1*13+6+e]); }
    for (int i = tid; i < 512; i += 256) { int lane=i&31, n=8*(i>>5)+(lane>>2), k=lane&3;
        bp1[i] = (k<3) ? f2t(W1[n*13+10+k]) : 0u; }
    for (int i = tid; i < 2560; i += 256) { int lane=i&31, kcnt=i>>5;
        int kc=kcnt/5, nt=kcnt-5*kc;
        int j=8*nt+(lane>>2), h0=8*kc+2*(lane&3);
        uint2 v; v.x=(j<39)?f2t(W2[j*128+h0]):0u; v.y=(j<39)?f2t(W2[j*128+h0+1]):0u;
        bp2[i]=v; }
    if (tid < 20) b2p[tid] = make_float2(b2[2*tid], (2*tid+1<39)? b2[2*tid+1] : 0.f);
    __syncthreads();

    const int w = tid >> 5, lane = tid & 31;
    const int q = lane & 3, r = lane >> 2;
#pragma unroll 1
    for (int i = 0; i < 2; i++) {
        const int lm  = (w*2 + i) * 16;
        const int slo = blockIdx.x*256 + lm + r, shi = slo + 8;
        float xl[4], xh[4];
#pragma unroll
        for (int e = 0; e < 4; e++) {
            int pidx = (q==0)? e : (q==1)? 10+e : 14+4*e;
            xl[e] = (q<3)? current_c[(size_t)slo*30+pidx] : 0.f;
            xh[e] = (q<3)? current_c[(size_t)shi*30+pidx] : 0.f;
        }
        float2 b2f[5];
#pragma unroll
        for (int n = 0; n < 5; n++) b2f[n] = b2p[4*n+q];
        float ss[5][4];
#pragma unroll
        for (int n=0;n<5;n++){ss[n][0]=0.f;ss[n][1]=0.f;ss[n][2]=0.f;ss[n][3]=0.f;}
#pragma unroll 1
        for (int e = 0; e < 4; e++) {
            u32 xa0 = f2t(xl[e]), xa1 = f2t(xh[e]);
            float D[5][4];
#pragma unroll
            for (int n=0;n<5;n++){D[n][0]=0.f;D[n][1]=0.f;D[n][2]=0.f;D[n][3]=0.f;}
#pragma unroll
            for (int kc = 0; kc < 16; kc++) {
                float2 cef = ce2[e*64 + kc*4 + q];
                float d0=cef.x, d1=cef.y, d2=cef.x, d3=cef.y;
                mma_k4(d0,d1,d2,d3, xa0, xa1, bp1[kc*32+lane]);
                u32 f0=f2t(fmaxf(d0,0.f)), f1=f2t(fmaxf(d2,0.f));
                u32 g0=f2t(fmaxf(d1,0.f)), g1=f2t(fmaxf(d3,0.f));
                const uint2* bb = bp2 + (kc*5)*32 + lane;
#pragma unroll
                for (int n=0;n<5;n++) {
                    uint2 b = bb[n*32];
                    mma_k8(D[n][0],D[n][1],D[n][2],D[n][3], f0,f1,g0,g1, b.x,b.y);
                }
            }
#pragma unroll
            for (int n=0;n<5;n++) {
                ss[n][0] += fmaxf(D[n][0]+b2f[n].x, 0.f);
                ss[n][1] += fmaxf(D[n][1]+b2f[n].y, 0.f);
                ss[n][2] += fmaxf(D[n][2]+b2f[n].x, 0.f);
                ss[n][3] += fmaxf(D[n][3]+b2f[n].y, 0.f);
            }
        }
#pragma unroll
        for (int n=0;n<5;n++) {
            int jp = 4*n + q;
            g_scr[(size_t)jp*bsz + slo] = pk2(ss[n][0], ss[n][1]);
            g_scr[(size_t)jp*bsz + shi] = pk2(ss[n][2], ss[n][3]);
        }
    }
}

// ================= Kernel B: trunk + heads + decoder (1 sample/thread) =================
__global__ void __launch_bounds__(256, 3)
tail_kernel(const float* __restrict__ initial_c, const float* __restrict__ eps,
            const float* __restrict__ W3, const float* __restrict__ b3,
            const float* __restrict__ Wm, const float* __restrict__ bm,
            const float* __restrict__ Wv, const float* __restrict__ bv,
            const float* __restrict__ Wd1, const float* __restrict__ bd1,
            const float* __restrict__ Wd2, const float* __restrict__ bd2,
            float* __restrict__ out, int bsz)
{
    __shared__ u64   w3p[128*20];   // j-pairs of W3 rows (col 39 -> 0)
    __shared__ float b3s[128];
    __shared__ u64   wmvp[128*8];   // o-pairs: 4x Wm | 4x Wv
    __shared__ u64   bmp[4], bvp[4];
    __shared__ u64   wd1p[32*10];   // feature-pairs of Wd1[:,5..24]
    __shared__ u64   wd2p[32*6];    // output-pairs of Wd2^T
    __shared__ float bd1s[32];
    __shared__ u64   bd2p[6];
    const int tid = threadIdx.x;

    for (int i = tid; i < 2560; i += 256) { int k=i/20, jp=i-k*20; int j0=2*jp, j1=j0+1;
        w3p[i] = pk2(j0<39? W3[k*39+j0]:0.f, j1<39? W3[k*39+j1]:0.f); }
    for (int i = tid; i < 128; i += 256) b3s[i] = b3[i];
    for (int i = tid; i < 1024; i += 256) { int k=i>>3, o=i&7; float a,b;
        if (o<4){a=Wm[2*o*128+k]; b=Wm[(2*o+1)*128+k];}
        else {int oo=o-4; a=Wv[2*oo*128+k]; b=Wv[(2*oo+1)*128+k];}
        wmvp[i]=pk2(a,b); }
    if (tid < 4) { bmp[tid]=pk2(bm[2*tid],bm[2*tid+1]); bvp[tid]=pk2(bv[2*tid],bv[2*tid+1]); }
    for (int i = tid; i < 320; i += 256) { int u=i/10, p=i-u*10;
        wd1p[i] = pk2(Wd1[u*25+5+2*p], Wd1[u*25+6+2*p]); }
    if (tid < 192) { int u=tid/6, rp=tid-u*6;
        wd2p[tid] = pk2(Wd2[2*rp*32+u], Wd2[(2*rp+1)*32+u]); }
    if (tid < 32) bd1s[tid] = bd1[tid] + Wd1[tid*25];
    if (tid < 6)  bd2p[tid] = pk2(bd2[2*tid], bd2[2*tid+1]);
    __syncthreads();

    const int s = blockIdx.x*256 + tid;
    u64 s40[20];
#pragma unroll
    for (int jp = 0; jp < 20; jp++) s40[jp] = g_scr[(size_t)jp*bsz + s];

    u64 mc[4], vc[4];
#pragma unroll
    for (int q = 0; q < 4; q++) { mc[q]=bmp[q]; vc[q]=bvp[q]; }
#pragma unroll 2
    for (int k = 0; k < 128; k++) {
        const ulonglong2* w = (const ulonglong2*)(w3p + k*20);
        u64 A=0ull, B=0ull, C=0ull, D=0ull;
#pragma unroll
        for (int p = 0; p < 5; p++) {
            ulonglong2 w01 = w[2*p], w23 = w[2*p+1];
            A = ffma2(s40[4*p],   w01.x, A);
            B = ffma2(s40[4*p+1], w01.y, B);
            C = ffma2(s40[4*p+2], w23.x, C);
            D = ffma2(s40[4*p+3], w23.y, D);
        }
        u64 t = fadd2(fadd2(A,B), fadd2(C,D));
        float x, y; unpk(t, x, y);
        float h = fmaxf(x + y + b3s[k], 0.f);
        u64 H = dup2(h);
        const ulonglong2* wmv = (const ulonglong2*)(wmvp + k*8);
        ulonglong2 wa=wmv[0], wb=wmv[1], wc2=wmv[2], wd=wmv[3];
        mc[0]=ffma2(H,wa.x,mc[0]);  mc[1]=ffma2(H,wa.y,mc[1]);
        mc[2]=ffma2(H,wb.x,mc[2]);  mc[3]=ffma2(H,wb.y,mc[3]);
        vc[0]=ffma2(H,wc2.x,vc[0]); vc[1]=ffma2(H,wc2.y,vc[1]);
        vc[2]=ffma2(H,wd.x,vc[2]);  vc[3]=ffma2(H,wd.y,vc[3]);
    }

    float me[8], lv[8];
#pragma unroll
    for (int q = 0; q < 4; q++) { unpk(mc[q], me[2*q], me[2*q+1]); unpk(vc[q], lv[2*q], lv[2*q+1]); }
    const float4* e4 = (const float4*)(eps + (size_t)s*8);
    float4 ea = e4[0], eb = e4[1];
    float ep[8] = {ea.x,ea.y,ea.z,ea.w, eb.x,eb.y,eb.z,eb.w};
    float z[8];
#pragma unroll
    for (int o = 0; o < 8; o++) z[o] = ep[o]*__expf(0.5f*lv[o]) + me[o];
    {
        float4* om = (float4*)(out + (size_t)bsz*12 + (size_t)s*8);
        float4* ov = (float4*)(out + (size_t)bsz*20 + (size_t)s*8);
        float4* oz = (float4*)(out + (size_t)bsz*28 + (size_t)s*8);
        om[0]=make_float4(me[0],me[1],me[2],me[3]); om[1]=make_float4(me[4],me[5],me[6],me[7]);
        ov[0]=make_float4(lv[0],lv[1],lv[2],lv[3]); ov[1]=make_float4(lv[4],lv[5],lv[6],lv[7]);
        oz[0]=make_float4(z[0],z[1],z[2],z[3]);     oz[1]=make_float4(z[4],z[5],z[6],z[7]);
    }

    // decoder
    const float* i0 = initial_c + (size_t)s*30;
    u64 fp[10];
    fp[0]=pk2(i0[0],i0[1]);   fp[1]=pk2(i0[2],i0[3]);
    fp[2]=pk2(i0[10],i0[11]); fp[3]=pk2(i0[12],i0[13]);
    fp[4]=pk2(i0[14],i0[18]); fp[5]=pk2(i0[22],i0[26]);
#pragma unroll
    for (int p = 0; p < 4; p++) fp[6+p] = pk2(z[2*p], z[2*p+1]);
    u64 d12[6];
#pragma unroll
    for (int rp = 0; rp < 6; rp++) d12[rp] = bd2p[rp];
#pragma unroll 4
    for (int u = 0; u < 32; u++) {
        const u64* w = wd1p + u*10;
        u64 A=0ull, B=0ull;
#pragma unroll
        for (int p = 0; p < 5; p++) {
            A = ffma2(fp[2*p],   w[2*p],   A);
            B = ffma2(fp[2*p+1], w[2*p+1], B);
        }
        u64 t = fadd2(A, B);
        float x, y; unpk(t, x, y);
        float h = fmaxf(x + y + bd1s[u], 0.f);
        u64 H = dup2(h);
        const u64* w2 = wd2p + u*6;
#pragma unroll
        for (int rp = 0; rp < 6; rp++) d12[rp] = ffma2(H, w2[rp], d12[rp]);
    }
    {
        float o[12];
#pragma unroll
        for (int rp = 0; rp < 6; rp++) {
            float x, y; unpk(d12[rp], x, y);
            o[2*rp]   = 1.f/(1.f+__expf(-x));
            o[2*rp+1] = 1.f/(1.f+__expf(-y));
        }
        float4* p = (float4*)(out + (size_t)s*12);
        p[0]=make_float4(o[0],o[1],o[2],o[3]);
        p[1]=make_float4(o[4],o[5],o[6],o[7]);
        p[2]=make_float4(o[8],o[9],o[10],o[11]);
    }
}

extern "C" void kernel_launch(void* const* d_in, const int* in_sizes, int n_in,
                              void* d_out, int out_size) {
    const float* initial_c = (const float*)d_in[0];
    const float* current_c = (const float*)d_in[2];
    const float* eps       = (const float*)d_in[3];
    const float* W1  = (const float*)d_in[4];
    const float* b1  = (const float*)d_in[5];
    const float* W2  = (const float*)d_in[6];
    const float* b2  = (const float*)d_in[7];
    const float* W3  = (const float*)d_in[8];
    const float* b3  = (const float*)d_in[9];
    const float* Wm  = (const float*)d_in[10];
    const float* bm  = (const float*)d_in[11];
    const float* Wv  = (const float*)d_in[12];
    const float* bv  = (const float*)d_in[13];
    const float* Wd1 = (const float*)d_in[14];
    const float* bd1 = (const float*)d_in[15];
    const float* Wd2 = (const float*)d_in[16];
    const float* bd2 = (const float*)d_in[17];
    float* out = (float*)d_out;

    int bsz = in_sizes[3] / 8;
    edge_kernel<<<bsz/256, 256>>>(current_c, W1, b1, W2, b2, bsz);
    tail_kernel<<<bsz/256, 256>>>(initial_c, eps, W3, b3, Wm, bm, Wv, bv,
                                  Wd1, bd1, Wd2, bd2, out, bsz);
}